// round 1
// baseline (speedup 1.0000x reference)
#include <cuda_runtime.h>
#include <cuda_bf16.h>
#include <math.h>

// Laplace diagonal recurrence:
//   out[t, i, f] = e[i] * out[t-1, i, f] + decay[i] * inp[t, f]
// T = 2048, N_S = 108, F = 256, fp32.
//
// Strategy: chunk T into 16 chunks of 128. Each block recomputes a 128-step
// warm-up from zero state (e_max^128 ~ 1.4e-10, negligible vs 1e-3 rel-err),
// then produces its 128 output rows. Each thread carries 4 i-states for a
// float2 of f, so each loaded inp value feeds 4 recurrences (cuts L2 read
// traffic 4x). Grid = 27 i-groups x 16 chunks.

constexpr int T_LEN  = 2048;
constexpr int F      = 256;
constexpr int NS     = 108;
constexpr int CHUNK  = 128;
constexpr int WARM   = 128;
constexpr int NCHUNK = T_LEN / CHUNK;   // 16
constexpr int GI     = 4;               // i-values per thread/block
constexpr int NIB    = NS / GI;         // 27 i-groups
constexpr int F2     = F / 2;           // 128 float2 lanes

__global__ __launch_bounds__(F2, 8)
void laplace_kernel(const float* __restrict__ inp, float* __restrict__ out) {
    const int f2    = threadIdx.x;   // 0..127 -> f pair
    const int ib    = blockIdx.x;    // 0..26
    const int chunk = blockIdx.y;    // 0..15

    // Per-i constants (computed once, double precision; matches the
    // reference's tau_star = (1+c)^(i-K), s = K/tau, e = exp(-s),
    // decay = (1-e)/s to well under fp32 precision).
    float e[GI], dcy[GI];
    const double c = pow(20.0, 1.0 / 99.0) - 1.0;
    #pragma unroll
    for (int g = 0; g < GI; g++) {
        int i = ib * GI + g;
        double tau = pow(1.0 + c, (double)(i - 4));
        double s   = 4.0 / tau;
        double ed  = exp(-s);
        e[g]   = (float)ed;
        dcy[g] = (float)((1.0 - ed) / s);
    }

    const int t_start = chunk * CHUNK;
    int t0 = t_start - WARM;
    if (t0 < 0) t0 = 0;

    const float2* __restrict__ inp2 = reinterpret_cast<const float2*>(inp);
    float2* __restrict__ out2       = reinterpret_cast<float2*>(out);

    float2 st[GI];
    #pragma unroll
    for (int g = 0; g < GI; g++) st[g] = make_float2(0.f, 0.f);

    const float2* ip = inp2 + (size_t)t0 * F2 + f2;

    // Warm-up: run the recurrence without storing. After WARM=128 steps the
    // neglected carry is <= e_max^128 ~ 1.4e-10 of a typical state value.
    const int warm_steps = t_start - t0;
    #pragma unroll 4
    for (int t = 0; t < warm_steps; ++t) {
        float2 x = __ldg(ip);
        ip += F2;
        #pragma unroll
        for (int g = 0; g < GI; g++) {
            st[g].x = fmaf(e[g], st[g].x, dcy[g] * x.x);
            st[g].y = fmaf(e[g], st[g].y, dcy[g] * x.y);
        }
    }

    // Main: 128 rows, store out[t, i, f].
    float2* op = out2 + (size_t)t_start * (NS * F2) + (size_t)(ib * GI) * F2 + f2;
    #pragma unroll 2
    for (int t = 0; t < CHUNK; ++t) {
        float2 x = __ldg(ip);
        ip += F2;
        #pragma unroll
        for (int g = 0; g < GI; g++) {
            st[g].x = fmaf(e[g], st[g].x, dcy[g] * x.x);
            st[g].y = fmaf(e[g], st[g].y, dcy[g] * x.y);
            op[g * F2] = st[g];
        }
        op += NS * F2;
    }
}

extern "C" void kernel_launch(void* const* d_in, const int* in_sizes, int n_in,
                              void* d_out, int out_size) {
    const float* inp = (const float*)d_in[0];
    float* out       = (float*)d_out;
    dim3 grid(NIB, NCHUNK);   // 27 x 16 = 432 blocks
    laplace_kernel<<<grid, F2>>>(inp, out);
}